// round 13
// baseline (speedup 1.0000x reference)
#include <cuda_runtime.h>
#include <cuda_bf16.h>
#include <cstdint>
#include <string.h>

#define BATCH 32
#define SEQT  512
#define INP   1024
#define HID   512
#define G     2048
#define NC    4
#define RNK   8
#define SCALING 2.0f
#define MROWS 16384   // BATCH*SEQT

// -------------------- device scratch (no allocations allowed) --------------------
__device__ __nv_bfloat16 g_wih_hi[(size_t)NC * G * INP];
__device__ __nv_bfloat16 g_wih_lo[(size_t)NC * G * INP];
__device__ __nv_bfloat16 g_whh_hi[(size_t)NC * G * HID];
__device__ __nv_bfloat16 g_whh_lo[(size_t)NC * G * HID];
__device__ __nv_bfloat16 g_xhi[(size_t)MROWS * INP];
__device__ __nv_bfloat16 g_xlo[(size_t)MROWS * INP];
__device__ __nv_bfloat16 g_l1hi[(size_t)MROWS * INP];
__device__ __nv_bfloat16 g_l1lo[(size_t)MROWS * INP];
__device__ float g_gx[2ull * MROWS * G];
__device__ __nv_bfloat16 g_hb16[2][2][2][BATCH * HID];  // [dir][pingpong][plane hi/lo]
__device__ unsigned g_bar[4];
__device__ unsigned g_gen[4];

// -------------------- helpers --------------------
__device__ __forceinline__ uint32_t smem_u32(const void* p)
{
    uint32_t a;
    asm("{ .reg .u64 t; cvta.to.shared.u64 t, %1; cvt.u32.u64 %0, t; }" : "=r"(a) : "l"(p));
    return a;
}
__device__ __forceinline__ void ldsm_x4(uint32_t& r0, uint32_t& r1, uint32_t& r2,
                                        uint32_t& r3, uint32_t addr)
{
    asm volatile("ldmatrix.sync.aligned.m8n8.x4.shared.b16 {%0,%1,%2,%3}, [%4];"
                 : "=r"(r0), "=r"(r1), "=r"(r2), "=r"(r3) : "r"(addr));
}
__device__ __forceinline__ void ldsm_x2(uint32_t& r0, uint32_t& r1, uint32_t addr)
{
    asm volatile("ldmatrix.sync.aligned.m8n8.x2.shared.b16 {%0,%1}, [%2];"
                 : "=r"(r0), "=r"(r1) : "r"(addr));
}
__device__ __forceinline__ void mma16816(float* d, const uint32_t* a, const uint32_t* b)
{
    asm volatile(
        "mma.sync.aligned.m16n8k16.row.col.f32.bf16.bf16.f32 "
        "{%0,%1,%2,%3}, {%4,%5,%6,%7}, {%8,%9}, {%0,%1,%2,%3};"
        : "+f"(d[0]), "+f"(d[1]), "+f"(d[2]), "+f"(d[3])
        : "r"(a[0]), "r"(a[1]), "r"(a[2]), "r"(a[3]), "r"(b[0]), "r"(b[1]));
}
__device__ __forceinline__ void cpasync16(uint32_t saddr, const void* g)
{
    asm volatile("cp.async.cg.shared.global [%0], [%1], 16;"
                 :: "r"(saddr), "l"(__cvta_generic_to_global(g)) : "memory");
}
#define CP_COMMIT() asm volatile("cp.async.commit_group;" ::: "memory")
#define CP_WAIT(n)  asm volatile("cp.async.wait_group %0;" :: "n"(n) : "memory")

__device__ __forceinline__ float sigm(float x) { return 1.f / (1.f + __expf(-x)); }

// -------------------- prep: fold LoRA + bf16-split --------------------
__global__ void prep_weff_ih(const float* __restrict__ w, const float* __restrict__ a,
                             const float* __restrict__ bl)
{
    size_t idx = (size_t)blockIdx.x * 256 + threadIdx.x;
    const size_t total = (size_t)NC * G * INP;
    if (idx >= total) return;
    int d = (int)(idx % INP);
    int g = (int)((idx / INP) % G);
    int c = (int)(idx / ((size_t)INP * G));
    const float* ar  = a  + (size_t)c * RNK * INP + d;
    const float* blr = bl + ((size_t)c * G + g) * RNK;
    float acc = 0.f;
#pragma unroll
    for (int r = 0; r < RNK; r++) acc += blr[r] * ar[(size_t)r * INP];
    float wv = w[idx] + SCALING * acc;
    __nv_bfloat16 hi = __float2bfloat16(wv);
    g_wih_hi[idx] = hi;
    g_wih_lo[idx] = __float2bfloat16(wv - __bfloat162float(hi));
}

__global__ void prep_weff_hh(const float* __restrict__ w, const float* __restrict__ a,
                             const float* __restrict__ bl)
{
    size_t idx = (size_t)blockIdx.x * 256 + threadIdx.x;
    const size_t total = (size_t)NC * G * HID;
    if (idx >= total) return;
    int d = (int)(idx % HID);
    int g = (int)((idx / HID) % G);
    int c = (int)(idx / ((size_t)HID * G));
    const float* ar  = a  + (size_t)c * RNK * HID + d;
    const float* blr = bl + ((size_t)c * G + g) * RNK;
    float acc = 0.f;
#pragma unroll
    for (int r = 0; r < RNK; r++) acc += blr[r] * ar[(size_t)r * HID];
    float wv = w[idx] + SCALING * acc;
    __nv_bfloat16 hi = __float2bfloat16(wv);
    g_whh_hi[idx] = hi;
    g_whh_lo[idx] = __float2bfloat16(wv - __bfloat162float(hi));
}

// -------------------- bf16-split x --------------------
__global__ void split_x(const float* __restrict__ src)
{
    size_t i = ((size_t)blockIdx.x * 256 + threadIdx.x) * 4;
    float4 v = *(const float4*)(src + i);
    __nv_bfloat16 h0 = __float2bfloat16(v.x), h1 = __float2bfloat16(v.y);
    __nv_bfloat16 h2 = __float2bfloat16(v.z), h3 = __float2bfloat16(v.w);
    __nv_bfloat16 l0 = __float2bfloat16(v.x - __bfloat162float(h0));
    __nv_bfloat16 l1 = __float2bfloat16(v.y - __bfloat162float(h1));
    __nv_bfloat16 l2 = __float2bfloat16(v.z - __bfloat162float(h2));
    __nv_bfloat16 l3 = __float2bfloat16(v.w - __bfloat162float(h3));
    __nv_bfloat162* hp = (__nv_bfloat162*)(g_xhi + i);
    __nv_bfloat162* lp = (__nv_bfloat162*)(g_xlo + i);
    hp[0] = __nv_bfloat162(h0, h1); hp[1] = __nv_bfloat162(h2, h3);
    lp[0] = __nv_bfloat162(l0, l1); lp[1] = __nv_bfloat162(l2, l3);
}

__global__ void reset_bar()
{
    if (threadIdx.x < 4) { g_bar[threadIdx.x] = 0u; g_gen[threadIdx.x] = 0u; }
}

// -------------------- tensor-core gx GEMM (unchanged, passing since R10) --------------------
#define RS     40
#define ABYTES (128 * RS * 2)
#define SMEM_GEMM (4 * ABYTES)

__global__ __launch_bounds__(256) void gemm_gx_mma(int layer,
                                                   const float* __restrict__ b_ih,
                                                   const float* __restrict__ b_hh)
{
    extern __shared__ __align__(16) char smem[];
    const uint32_t sb = smem_u32(smem);
    const int tid = threadIdx.x, wid = tid >> 5, lane = tid & 31;
    const int wm = wid >> 2, wn = wid & 3;
    const int n0 = blockIdx.x * 128, m0 = blockIdx.y * 128, cl = blockIdx.z;
    const int cell = layer * 2 + cl;

    const __nv_bfloat16* Ah = layer ? g_l1hi : g_xhi;
    const __nv_bfloat16* Al = layer ? g_l1lo : g_xlo;
    const __nv_bfloat16* Bh = g_wih_hi + (size_t)cell * G * INP;
    const __nv_bfloat16* Bl = g_wih_lo + (size_t)cell * G * INP;

    float acc[4][4][4];
#pragma unroll
    for (int i = 0; i < 4; i++)
#pragma unroll
        for (int j = 0; j < 4; j++)
#pragma unroll
            for (int q = 0; q < 4; q++) acc[i][j][q] = 0.f;

    const int lrow = tid >> 2, lc8 = (tid & 3) * 8;

    auto load_chunk = [&](int ch, int buf) {
        const int plane = ch >> 5;
        const int kc = (ch & 31) * 32;
        const __nv_bfloat16* Ap = (plane == 2) ? Al : Ah;
        const __nv_bfloat16* Bp = (plane == 1) ? Bl : Bh;
        uint32_t sa = sb + buf * ABYTES;
        uint32_t sB = sb + 2 * ABYTES + buf * ABYTES;
        cpasync16(sa + (lrow * RS + lc8) * 2,        Ap + (size_t)(m0 + lrow)      * INP + kc + lc8);
        cpasync16(sa + ((lrow + 64) * RS + lc8) * 2, Ap + (size_t)(m0 + lrow + 64) * INP + kc + lc8);
        cpasync16(sB + (lrow * RS + lc8) * 2,        Bp + (size_t)(n0 + lrow)      * INP + kc + lc8);
        cpasync16(sB + ((lrow + 64) * RS + lc8) * 2, Bp + (size_t)(n0 + lrow + 64) * INP + kc + lc8);
        CP_COMMIT();
    };

    const int arow = wm * 64 + (lane & 15);
    const int acol_sel = (lane >> 4) * 8;
    const int brow = wn * 32 + (lane & 7);
    const int bcol_sel = ((lane >> 3) & 1) * 8;

    load_chunk(0, 0);

    for (int ch = 0; ch < 96; ch++) {
        const int b = ch & 1;
        if (ch < 95) load_chunk(ch + 1, 1 - b);
        if (ch < 95) { CP_WAIT(1); } else { CP_WAIT(0); }
        __syncthreads();

        const uint32_t sa = sb + b * ABYTES;
        const uint32_t sB = sb + 2 * ABYTES + b * ABYTES;
#pragma unroll
        for (int ks = 0; ks < 2; ks++) {
            uint32_t afr[4][4], bfr[4][2];
#pragma unroll
            for (int mt = 0; mt < 4; mt++) {
                uint32_t addr = sa + ((arow + mt * 16) * RS + ks * 16 + acol_sel) * 2;
                ldsm_x4(afr[mt][0], afr[mt][1], afr[mt][2], afr[mt][3], addr);
            }
#pragma unroll
            for (int nt = 0; nt < 4; nt++) {
                uint32_t addr = sB + ((brow + nt * 8) * RS + ks * 16 + bcol_sel) * 2;
                ldsm_x2(bfr[nt][0], bfr[nt][1], addr);
            }
#pragma unroll
            for (int mt = 0; mt < 4; mt++)
#pragma unroll
                for (int nt = 0; nt < 4; nt++)
                    mma16816(acc[mt][nt], afr[mt], bfr[nt]);
        }
        __syncthreads();
    }

    float bsum[4][2];
#pragma unroll
    for (int nt = 0; nt < 4; nt++) {
        int col = n0 + wn * 32 + nt * 8 + (lane & 3) * 2;
        bsum[nt][0] = b_ih[(size_t)cell * G + col]     + b_hh[(size_t)cell * G + col];
        bsum[nt][1] = b_ih[(size_t)cell * G + col + 1] + b_hh[(size_t)cell * G + col + 1];
    }
    float* gxbase = g_gx + (size_t)cl * MROWS * G;
#pragma unroll
    for (int mt = 0; mt < 4; mt++) {
        int r0 = m0 + wm * 64 + mt * 16 + (lane >> 2);
        float* row0 = gxbase + (size_t)r0 * G;
        float* row1 = row0 + 8 * (size_t)G;
#pragma unroll
        for (int nt = 0; nt < 4; nt++) {
            int col = n0 + wn * 32 + nt * 8 + (lane & 3) * 2;
            float2 v0 = make_float2(acc[mt][nt][0] + bsum[nt][0],
                                    acc[mt][nt][1] + bsum[nt][1]);
            float2 v1 = make_float2(acc[mt][nt][2] + bsum[nt][0],
                                    acc[mt][nt][3] + bsum[nt][1]);
            *(float2*)(row0 + col) = v0;
            *(float2*)(row1 + col) = v1;
        }
    }
}

// -------------------- persistent recurrence v2 --------------------
// 128 CTAs = dir(2) x batch-half(2) x unit-group(32, 16 units each).
// smem: h (16 batches, hi/lo) + W (64 gate rows, hi/lo) + P tile.
// W smem row R: gate = R&3, unit = j0 + (R>>2).  Warp w owns rows [16w,16w+16).
#define HROW 1040                       // bytes per smem row (520 bf16)
#define SH0  0
#define SH1  (SH0 + 16 * HROW)          // 16640
#define SW0  (SH1 + 16 * HROW)          // 33280
#define SW1  (SW0 + 64 * HROW)          // 99840
#define SP   (SW1 + 64 * HROW)          // 166400
#define PST  68                         // P stride (floats)
#define SMEM_REC (SP + 16 * PST * 4 + 128)

__global__ __launch_bounds__(128, 1) void lstm_rec(int layer, float* __restrict__ dout)
{
    extern __shared__ __align__(16) char smc[];
    const uint32_t sb = smem_u32(smc);
    float* Pt = (float*)(smc + SP);

    const int cta  = blockIdx.x;
    const int dir  = cta >> 6;
    const int bh   = (cta >> 5) & 1;
    const int ug   = cta & 31;
    const int j0   = ug * 16;
    const int grp  = dir * 2 + bh;
    const int cell = layer * 2 + dir;
    const int tid  = threadIdx.x;
    const int wid  = tid >> 5, lane = tid & 31;

    // load W slice (64 reordered rows, both planes)
    {
        const __nv_bfloat16* srcs[2] = { g_whh_hi + (size_t)cell * G * HID,
                                         g_whh_lo + (size_t)cell * G * HID };
        const uint32_t dsts[2] = { SW0, SW1 };
#pragma unroll
        for (int p = 0; p < 2; p++) {
            for (int i = tid; i < 64 * 64; i += 128) {
                int R = i >> 6, k8 = (i & 63) * 8;
                int gate = R & 3;
                int urow = j0 + (R >> 2);
                const uint4 v = *(const uint4*)(srcs[p] + (size_t)(gate * HID + urow) * HID + k8);
                *(uint4*)(smc + dsts[p] + R * HROW + k8 * 2) = v;
            }
        }
    }
    // zero h smem (both planes)
    for (int i = tid; i < (2 * 16 * HROW) / 4; i += 128) ((uint32_t*)(smc + SH0))[i] = 0u;
    __syncthreads();

    // fragment bases
    const uint32_t ah_b = sb + SH0 + (uint32_t)((lane & 15) * HROW + (lane >> 4) * 16);
    const uint32_t al_b = sb + SH1 + (uint32_t)((lane & 15) * HROW + (lane >> 4) * 16);
    const uint32_t bh_b = sb + SW0 + (uint32_t)((wid * 16 + (lane & 7)) * HROW + (lane >> 3) * 16);
    const uint32_t bl_b = sb + SW1 + (uint32_t)((wid * 16 + (lane & 7)) * HROW + (lane >> 3) * 16);

    const int u  = tid & 15;            // unit within group
    const int bp = tid >> 4;            // 0..7 -> local batches 2bp, 2bp+1
    const int lb0 = bp * 2, lb1 = lb0 + 1;
    const int B0 = bh * 16 + lb0, B1 = bh * 16 + lb1;   // global batches
    const int j  = j0 + u;
    const float* gx = g_gx + (size_t)dir * MROWS * G;

    float c0 = 0.f, c1 = 0.f, h0v = 0.f, h1v = 0.f;

    for (int s = 0; s < SEQT; s++) {
        const int t = dir ? (SEQT - 1 - s) : s;

        if (s > 0) {   // stage this half's h(s-1) planes into smem
            const __nv_bfloat16* s0 = g_hb16[dir][(s - 1) & 1][0] + bh * 16 * HID;
            const __nv_bfloat16* s1 = g_hb16[dir][(s - 1) & 1][1] + bh * 16 * HID;
            for (int i = tid; i < 1024; i += 128) {
                int b = i >> 6, k8 = (i & 63) * 8;
                *(uint4*)(smc + SH0 + b * HROW + k8 * 2) = *(const uint4*)(s0 + b * HID + k8);
                *(uint4*)(smc + SH1 + b * HROW + k8 * 2) = *(const uint4*)(s1 + b * HID + k8);
            }
            __syncthreads();
        }

        // prefetch gx operands
        size_t gxo0 = ((size_t)(B0 * SEQT + t)) * G + j;
        size_t gxo1 = ((size_t)(B1 * SEQT + t)) * G + j;
        float xi0 = gx[gxo0],        xf0 = gx[gxo0 + 512];
        float xg0 = gx[gxo0 + 1024], xo0 = gx[gxo0 + 1536];
        float xi1 = gx[gxo1],        xf1 = gx[gxo1 + 512];
        float xg1 = gx[gxo1 + 1024], xo1 = gx[gxo1 + 1536];

        // P = Hhi*Whi + Hhi*Wlo + Hlo*Whi   (warp: 2 n-tiles of 8 rows)
        float acc[2][4];
#pragma unroll
        for (int m = 0; m < 2; m++)
#pragma unroll
            for (int q = 0; q < 4; q++) acc[m][q] = 0.f;

#pragma unroll 2
        for (int kt2 = 0; kt2 < 16; kt2++) {
            const uint32_t kb = (uint32_t)kt2 * 64;
            uint32_t ah0[4], ah1[4], al0[4], al1[4];
            ldsm_x4(ah0[0], ah0[1], ah0[2], ah0[3], ah_b + kb);
            ldsm_x4(ah1[0], ah1[1], ah1[2], ah1[3], ah_b + kb + 32);
            ldsm_x4(al0[0], al0[1], al0[2], al0[3], al_b + kb);
            ldsm_x4(al1[0], al1[1], al1[2], al1[3], al_b + kb + 32);
#pragma unroll
            for (int nt = 0; nt < 2; nt++) {
                uint32_t bhf[4], blf[4];
                ldsm_x4(bhf[0], bhf[1], bhf[2], bhf[3], bh_b + nt * 8 * HROW + kb);
                ldsm_x4(blf[0], blf[1], blf[2], blf[3], bl_b + nt * 8 * HROW + kb);
                mma16816(acc[nt], ah0, bhf);        // regs {0,1} = first k16
                mma16816(acc[nt], ah0, blf);
                mma16816(acc[nt], al0, bhf);
                mma16816(acc[nt], ah1, bhf + 2);    // regs {2,3} = second k16
                mma16816(acc[nt], ah1, blf + 2);
                mma16816(acc[nt], al1, bhf + 2);
            }
        }

        // accumulators -> P smem tile: row = batch(0..15), col = gate-row R
        {
            int prow = lane >> 2;
            int pcol = wid * 16 + 2 * (lane & 3);
#pragma unroll
            for (int nt = 0; nt < 2; nt++) {
                *(float2*)&Pt[prow * PST + pcol + nt * 8]       = make_float2(acc[nt][0], acc[nt][1]);
                *(float2*)&Pt[(prow + 8) * PST + pcol + nt * 8] = make_float2(acc[nt][2], acc[nt][3]);
            }
        }
        __syncthreads();

        // epilogue: thread = (2 local batches, 1 unit); P col for gate g = u*4+g
        float4 P0 = *(float4*)&Pt[lb0 * PST + u * 4];
        float4 P1 = *(float4*)&Pt[lb1 * PST + u * 4];
        float gi0 = xi0 + P0.x, gf0 = xf0 + P0.y, gg0 = xg0 + P0.z, go0 = xo0 + P0.w;
        float gi1 = xi1 + P1.x, gf1 = xf1 + P1.y, gg1 = xg1 + P1.z, go1 = xo1 + P1.w;

        c0  = sigm(gf0) * c0 + sigm(gi0) * tanhf(gg0);
        h0v = sigm(go0) * tanhf(c0);
        c1  = sigm(gf1) * c1 + sigm(gi1) * tanhf(gg1);
        h1v = sigm(go1) * tanhf(c1);

        __nv_bfloat16 hh0 = __float2bfloat16(h0v);
        __nv_bfloat16 hl0 = __float2bfloat16(h0v - __bfloat162float(hh0));
        __nv_bfloat16 hh1 = __float2bfloat16(h1v);
        __nv_bfloat16 hl1 = __float2bfloat16(h1v - __bfloat162float(hh1));
        g_hb16[dir][s & 1][0][B0 * HID + j] = hh0;
        g_hb16[dir][s & 1][1][B0 * HID + j] = hl0;
        g_hb16[dir][s & 1][0][B1 * HID + j] = hh1;
        g_hb16[dir][s & 1][1][B1 * HID + j] = hl1;
        if (layer == 0) {
            size_t r0o = ((size_t)(B0 * SEQT + t)) * INP + dir * HID + j;
            size_t r1o = ((size_t)(B1 * SEQT + t)) * INP + dir * HID + j;
            g_l1hi[r0o] = hh0; g_l1lo[r0o] = hl0;
            g_l1hi[r1o] = hh1; g_l1lo[r1o] = hl1;
        } else {
            dout[((size_t)B0 * SEQT + t) * (2 * HID) + dir * HID + j] = h0v;
            dout[((size_t)B1 * SEQT + t) * (2 * HID) + dir * HID + j] = h1v;
        }

        if (s < SEQT - 1) {
            __syncthreads();
            if (tid == 0) {
                __threadfence();
                unsigned arr = atomicAdd(&g_bar[grp], 1u);
                if (arr == 31u) {
                    atomicExch(&g_bar[grp], 0u);
                    __threadfence();
                    atomicAdd(&g_gen[grp], 1u);
                } else {
                    unsigned target = (unsigned)(layer * (SEQT - 1) + s + 1);
                    while (*((volatile unsigned*)&g_gen[grp]) < target) { }
                    __threadfence();
                }
            }
            __syncthreads();
        }
    }

    float* hn = dout + (size_t)MROWS * 2 * HID;
    float* cn = hn + (size_t)NC * BATCH * HID;
    size_t o0 = ((size_t)cell * BATCH + B0) * HID + j;
    size_t o1 = ((size_t)cell * BATCH + B1) * HID + j;
    hn[o0] = h0v; hn[o1] = h1v;
    cn[o0] = c0;  cn[o1] = c1;
}

// -------------------- launch --------------------
extern "C" void kernel_launch(void* const* d_in, const int* in_sizes, int n_in,
                              void* d_out, int out_size)
{
    (void)in_sizes; (void)n_in; (void)out_size;
    const float* x     = (const float*)d_in[0];
    const float* w_ih  = (const float*)d_in[1];
    const float* w_hh  = (const float*)d_in[2];
    const float* b_ih  = (const float*)d_in[3];
    const float* b_hh  = (const float*)d_in[4];
    const float* a_ih  = (const float*)d_in[5];
    const float* bl_ih = (const float*)d_in[6];
    const float* a_hh  = (const float*)d_in[7];
    const float* bl_hh = (const float*)d_in[8];
    float* out = (float*)d_out;

    cudaFuncSetAttribute(lstm_rec, cudaFuncAttributeMaxDynamicSharedMemorySize, SMEM_REC);
    cudaFuncSetAttribute(gemm_gx_mma, cudaFuncAttributeMaxDynamicSharedMemorySize, SMEM_GEMM);

    size_t tih = (size_t)NC * G * INP;
    prep_weff_ih<<<(unsigned)((tih + 255) / 256), 256>>>(w_ih, a_ih, bl_ih);
    size_t thh = (size_t)NC * G * HID;
    prep_weff_hh<<<(unsigned)((thh + 255) / 256), 256>>>(w_hh, a_hh, bl_hh);
    split_x<<<(unsigned)((size_t)MROWS * INP / 1024), 256>>>(x);
    reset_bar<<<1, 32>>>();

    // ---- layer 0 ----
    gemm_gx_mma<<<dim3(16, 128, 2), 256, SMEM_GEMM>>>(0, b_ih, b_hh);
    lstm_rec<<<128, 128, SMEM_REC>>>(0, out);

    // ---- layer 1 ----
    gemm_gx_mma<<<dim3(16, 128, 2), 256, SMEM_GEMM>>>(1, b_ih, b_hh);
    lstm_rec<<<128, 128, SMEM_REC>>>(1, out);
}

// round 15
// speedup vs baseline: 1.2784x; 1.2784x over previous
#include <cuda_runtime.h>
#include <cuda_bf16.h>
#include <cstdint>
#include <string.h>

#define BATCH 32
#define SEQT  512
#define INP   1024
#define HID   512
#define G     2048
#define NC    4
#define RNK   8
#define SCALING 2.0f
#define MROWS 16384   // BATCH*SEQT

// -------------------- device scratch (no allocations allowed) --------------------
__device__ __nv_bfloat16 g_wih_hi[(size_t)NC * G * INP];
__device__ __nv_bfloat16 g_wih_lo[(size_t)NC * G * INP];
__device__ __nv_bfloat16 g_whh_hi[(size_t)NC * G * HID];
__device__ __nv_bfloat16 g_whh_lo[(size_t)NC * G * HID];
__device__ __nv_bfloat16 g_xhi[(size_t)MROWS * INP];
__device__ __nv_bfloat16 g_xlo[(size_t)MROWS * INP];
__device__ __nv_bfloat16 g_l1hi[(size_t)MROWS * INP];
__device__ __nv_bfloat16 g_l1lo[(size_t)MROWS * INP];
__device__ float g_gx[2ull * MROWS * G];
__device__ __nv_bfloat16 g_hb16[2][2][2][BATCH * HID];  // [dir][pingpong][plane hi/lo]
__device__ unsigned g_bar[2];
__device__ unsigned g_gen[2];

// -------------------- helpers --------------------
__device__ __forceinline__ uint32_t smem_u32(const void* p)
{
    uint32_t a;
    asm("{ .reg .u64 t; cvta.to.shared.u64 t, %1; cvt.u32.u64 %0, t; }" : "=r"(a) : "l"(p));
    return a;
}
__device__ __forceinline__ void ldsm_x4(uint32_t& r0, uint32_t& r1, uint32_t& r2,
                                        uint32_t& r3, uint32_t addr)
{
    asm volatile("ldmatrix.sync.aligned.m8n8.x4.shared.b16 {%0,%1,%2,%3}, [%4];"
                 : "=r"(r0), "=r"(r1), "=r"(r2), "=r"(r3) : "r"(addr));
}
__device__ __forceinline__ void ldsm_x2(uint32_t& r0, uint32_t& r1, uint32_t addr)
{
    asm volatile("ldmatrix.sync.aligned.m8n8.x2.shared.b16 {%0,%1}, [%2];"
                 : "=r"(r0), "=r"(r1) : "r"(addr));
}
__device__ __forceinline__ void mma16816(float* d, const uint32_t* a, const uint32_t* b)
{
    asm volatile(
        "mma.sync.aligned.m16n8k16.row.col.f32.bf16.bf16.f32 "
        "{%0,%1,%2,%3}, {%4,%5,%6,%7}, {%8,%9}, {%0,%1,%2,%3};"
        : "+f"(d[0]), "+f"(d[1]), "+f"(d[2]), "+f"(d[3])
        : "r"(a[0]), "r"(a[1]), "r"(a[2]), "r"(a[3]), "r"(b[0]), "r"(b[1]));
}
__device__ __forceinline__ void cpasync16(uint32_t saddr, const void* g)
{
    asm volatile("cp.async.cg.shared.global [%0], [%1], 16;"
                 :: "r"(saddr), "l"(__cvta_generic_to_global(g)) : "memory");
}
#define CP_COMMIT() asm volatile("cp.async.commit_group;" ::: "memory")
#define CP_WAIT(n)  asm volatile("cp.async.wait_group %0;" :: "n"(n) : "memory")

__device__ __forceinline__ float sigm(float x) { return 1.f / (1.f + __expf(-x)); }

// -------------------- merged prep: fold LoRA + bf16-split + split x --------------------
// idx ranges: [0, NIH) ih fold/split; [NIH, NIH+NHH) hh fold/split;
// [NIH+NHH, NIH+NHH+NXQ) x split (4 floats per thread). Block 0 also resets bars.
#define NIH ((size_t)NC * G * INP)     // 8388608
#define NHH ((size_t)NC * G * HID)     // 4194304
#define NXQ ((size_t)MROWS * INP / 4)  // 4194304

__global__ void prep_all(const float* __restrict__ w_ih, const float* __restrict__ a_ih,
                         const float* __restrict__ bl_ih,
                         const float* __restrict__ w_hh, const float* __restrict__ a_hh,
                         const float* __restrict__ bl_hh,
                         const float* __restrict__ x)
{
    size_t idx = (size_t)blockIdx.x * 256 + threadIdx.x;
    if (idx < NIH) {
        int d = (int)(idx % INP);
        int g = (int)((idx / INP) % G);
        int c = (int)(idx / ((size_t)INP * G));
        const float* ar  = a_ih + (size_t)c * RNK * INP + d;
        const float* blr = bl_ih + ((size_t)c * G + g) * RNK;
        float acc = 0.f;
#pragma unroll
        for (int r = 0; r < RNK; r++) acc += blr[r] * ar[(size_t)r * INP];
        float wv = w_ih[idx] + SCALING * acc;
        __nv_bfloat16 hi = __float2bfloat16(wv);
        g_wih_hi[idx] = hi;
        g_wih_lo[idx] = __float2bfloat16(wv - __bfloat162float(hi));
    } else if (idx < NIH + NHH) {
        size_t k = idx - NIH;
        int d = (int)(k % HID);
        int g = (int)((k / HID) % G);
        int c = (int)(k / ((size_t)HID * G));
        const float* ar  = a_hh + (size_t)c * RNK * HID + d;
        const float* blr = bl_hh + ((size_t)c * G + g) * RNK;
        float acc = 0.f;
#pragma unroll
        for (int r = 0; r < RNK; r++) acc += blr[r] * ar[(size_t)r * HID];
        float wv = w_hh[k] + SCALING * acc;
        __nv_bfloat16 hi = __float2bfloat16(wv);
        g_whh_hi[k] = hi;
        g_whh_lo[k] = __float2bfloat16(wv - __bfloat162float(hi));
    } else {
        size_t q = (idx - NIH - NHH) * 4;
        float4 v = *(const float4*)(x + q);
        __nv_bfloat16 h0 = __float2bfloat16(v.x), h1 = __float2bfloat16(v.y);
        __nv_bfloat16 h2 = __float2bfloat16(v.z), h3 = __float2bfloat16(v.w);
        __nv_bfloat16 l0 = __float2bfloat16(v.x - __bfloat162float(h0));
        __nv_bfloat16 l1 = __float2bfloat16(v.y - __bfloat162float(h1));
        __nv_bfloat16 l2 = __float2bfloat16(v.z - __bfloat162float(h2));
        __nv_bfloat16 l3 = __float2bfloat16(v.w - __bfloat162float(h3));
        __nv_bfloat162* hp = (__nv_bfloat162*)(g_xhi + q);
        __nv_bfloat162* lp = (__nv_bfloat162*)(g_xlo + q);
        hp[0] = __nv_bfloat162(h0, h1); hp[1] = __nv_bfloat162(h2, h3);
        lp[0] = __nv_bfloat162(l0, l1); lp[1] = __nv_bfloat162(l2, l3);
    }
}

__global__ void reset_bar()
{
    if (threadIdx.x < 2) { g_bar[threadIdx.x] = 0u; g_gen[threadIdx.x] = 0u; }
}

// -------------------- tensor-core gx GEMM (unchanged, passing since R10) --------------------
#define RS     40
#define ABYTES (128 * RS * 2)
#define SMEM_GEMM (4 * ABYTES)

__global__ __launch_bounds__(256) void gemm_gx_mma(int layer,
                                                   const float* __restrict__ b_ih,
                                                   const float* __restrict__ b_hh)
{
    extern __shared__ __align__(16) char smem[];
    const uint32_t sb = smem_u32(smem);
    const int tid = threadIdx.x, wid = tid >> 5, lane = tid & 31;
    const int wm = wid >> 2, wn = wid & 3;
    const int n0 = blockIdx.x * 128, m0 = blockIdx.y * 128, cl = blockIdx.z;
    const int cell = layer * 2 + cl;

    const __nv_bfloat16* Ah = layer ? g_l1hi : g_xhi;
    const __nv_bfloat16* Al = layer ? g_l1lo : g_xlo;
    const __nv_bfloat16* Bh = g_wih_hi + (size_t)cell * G * INP;
    const __nv_bfloat16* Bl = g_wih_lo + (size_t)cell * G * INP;

    float acc[4][4][4];
#pragma unroll
    for (int i = 0; i < 4; i++)
#pragma unroll
        for (int j = 0; j < 4; j++)
#pragma unroll
            for (int q = 0; q < 4; q++) acc[i][j][q] = 0.f;

    const int lrow = tid >> 2, lc8 = (tid & 3) * 8;

    auto load_chunk = [&](int ch, int buf) {
        const int plane = ch >> 5;
        const int kc = (ch & 31) * 32;
        const __nv_bfloat16* Ap = (plane == 2) ? Al : Ah;
        const __nv_bfloat16* Bp = (plane == 1) ? Bl : Bh;
        uint32_t sa = sb + buf * ABYTES;
        uint32_t sB = sb + 2 * ABYTES + buf * ABYTES;
        cpasync16(sa + (lrow * RS + lc8) * 2,        Ap + (size_t)(m0 + lrow)      * INP + kc + lc8);
        cpasync16(sa + ((lrow + 64) * RS + lc8) * 2, Ap + (size_t)(m0 + lrow + 64) * INP + kc + lc8);
        cpasync16(sB + (lrow * RS + lc8) * 2,        Bp + (size_t)(n0 + lrow)      * INP + kc + lc8);
        cpasync16(sB + ((lrow + 64) * RS + lc8) * 2, Bp + (size_t)(n0 + lrow + 64) * INP + kc + lc8);
        CP_COMMIT();
    };

    const int arow = wm * 64 + (lane & 15);
    const int acol_sel = (lane >> 4) * 8;
    const int brow = wn * 32 + (lane & 7);
    const int bcol_sel = ((lane >> 3) & 1) * 8;

    load_chunk(0, 0);

    for (int ch = 0; ch < 96; ch++) {
        const int b = ch & 1;
        if (ch < 95) load_chunk(ch + 1, 1 - b);
        if (ch < 95) { CP_WAIT(1); } else { CP_WAIT(0); }
        __syncthreads();

        const uint32_t sa = sb + b * ABYTES;
        const uint32_t sB = sb + 2 * ABYTES + b * ABYTES;
#pragma unroll
        for (int ks = 0; ks < 2; ks++) {
            uint32_t afr[4][4], bfr[4][2];
#pragma unroll
            for (int mt = 0; mt < 4; mt++) {
                uint32_t addr = sa + ((arow + mt * 16) * RS + ks * 16 + acol_sel) * 2;
                ldsm_x4(afr[mt][0], afr[mt][1], afr[mt][2], afr[mt][3], addr);
            }
#pragma unroll
            for (int nt = 0; nt < 4; nt++) {
                uint32_t addr = sB + ((brow + nt * 8) * RS + ks * 16 + bcol_sel) * 2;
                ldsm_x2(bfr[nt][0], bfr[nt][1], addr);
            }
#pragma unroll
            for (int mt = 0; mt < 4; mt++)
#pragma unroll
                for (int nt = 0; nt < 4; nt++)
                    mma16816(acc[mt][nt], afr[mt], bfr[nt]);
        }
        __syncthreads();
    }

    float bsum[4][2];
#pragma unroll
    for (int nt = 0; nt < 4; nt++) {
        int col = n0 + wn * 32 + nt * 8 + (lane & 3) * 2;
        bsum[nt][0] = b_ih[(size_t)cell * G + col]     + b_hh[(size_t)cell * G + col];
        bsum[nt][1] = b_ih[(size_t)cell * G + col + 1] + b_hh[(size_t)cell * G + col + 1];
    }
    float* gxbase = g_gx + (size_t)cl * MROWS * G;
#pragma unroll
    for (int mt = 0; mt < 4; mt++) {
        int r0 = m0 + wm * 64 + mt * 16 + (lane >> 2);
        float* row0 = gxbase + (size_t)r0 * G;
        float* row1 = row0 + 8 * (size_t)G;
#pragma unroll
        for (int nt = 0; nt < 4; nt++) {
            int col = n0 + wn * 32 + nt * 8 + (lane & 3) * 2;
            float2 v0 = make_float2(acc[mt][nt][0] + bsum[nt][0],
                                    acc[mt][nt][1] + bsum[nt][1]);
            float2 v1 = make_float2(acc[mt][nt][2] + bsum[nt][0],
                                    acc[mt][nt][3] + bsum[nt][1]);
            *(float2*)(row0 + col) = v0;
            *(float2*)(row1 + col) = v1;
        }
    }
}

// -------------------- persistent recurrence (R12 layout + split accumulators) ----------
// 128 CTAs: dir = cta>>6, 8 hidden units each. smem: h hi/lo + W hi/lo + P tile.
// W rows reordered: smem row R -> gate=(R&7)>>1, unit = j0 + 2*(R>>3) + (R&1).
// Warp w owns n-tile rows [8w, 8w+8) = units 2w, 2w+1.
#define HROW 1040                 // bytes per smem row (520 bf16)
#define SH0  0
#define SH1  (SH0 + 32 * HROW)    // 33280
#define SW0  (SH1 + 32 * HROW)
#define SW1  (SW0 + 32 * HROW)
#define SP   (SW1 + 32 * HROW)    // 133120
#define PST  34                   // P stride (floats)
#define SMEM_REC (SP + 32 * PST * 4 + 128)

__global__ __launch_bounds__(128, 1) void lstm_rec(int layer, float* __restrict__ dout)
{
    extern __shared__ __align__(16) char smc[];
    const uint32_t sb = smem_u32(smc);
    float* Pt = (float*)(smc + SP);

    const int cta  = blockIdx.x;
    const int dir  = cta >> 6;
    const int j0   = (cta & 63) * 8;
    const int cell = layer * 2 + dir;
    const int tid  = threadIdx.x;
    const int wid  = tid >> 5, lane = tid & 31;

    // load W slice (both planes), reordered rows
    {
        const __nv_bfloat16* srcs[2] = { g_whh_hi + (size_t)cell * G * HID,
                                         g_whh_lo + (size_t)cell * G * HID };
        const uint32_t dsts[2] = { SW0, SW1 };
#pragma unroll
        for (int p = 0; p < 2; p++) {
            for (int i = tid; i < 2048; i += 128) {
                int R = i >> 6, k8 = (i & 63) * 8;
                int gate = (R & 7) >> 1;
                int urow = 2 * (R >> 3) + (R & 1);
                const uint4 v = *(const uint4*)(srcs[p] + (size_t)(gate * HID + j0 + urow) * HID + k8);
                *(uint4*)(smc + dsts[p] + R * HROW + k8 * 2) = v;
            }
        }
    }
    for (int i = tid; i < (2 * 32 * HROW) / 4; i += 128) ((uint32_t*)(smc + SH0))[i] = 0u;
    __syncthreads();

    const uint32_t aoff = (uint32_t)((lane & 15) * HROW + (lane >> 4) * 16);
    const uint32_t boff = (uint32_t)(wid * 8 * HROW + (lane & 7) * HROW + ((lane >> 3) & 1) * 16);
    const uint32_t ah_b = sb + SH0 + aoff, al_b = sb + SH1 + aoff;
    const uint32_t bh_b = sb + SW0 + boff, bl_b = sb + SW1 + boff;

    const int bp = tid >> 3;
    const int u  = tid & 7;
    const int b0 = bp * 2, b1 = b0 + 1;
    const int j  = j0 + u;
    const int Rg0 = (u >> 1) * 8 + (u & 1);
    const float* gx = g_gx + (size_t)dir * MROWS * G;

    float c0 = 0.f, c1 = 0.f, h0v = 0.f, h1v = 0.f;

    for (int s = 0; s < SEQT; s++) {
        const int t = dir ? (SEQT - 1 - s) : s;

        if (s > 0) {
            const __nv_bfloat16* s0 = g_hb16[dir][(s - 1) & 1][0];
            const __nv_bfloat16* s1 = g_hb16[dir][(s - 1) & 1][1];
            for (int i = tid; i < 2048; i += 128) {
                int b = i >> 6, k8 = (i & 63) * 8;
                *(uint4*)(smc + SH0 + b * HROW + k8 * 2) = *(const uint4*)(s0 + b * HID + k8);
                *(uint4*)(smc + SH1 + b * HROW + k8 * 2) = *(const uint4*)(s1 + b * HID + k8);
            }
            __syncthreads();
        }

        size_t gxo0 = ((size_t)(b0 * SEQT + t)) * G + j;
        size_t gxo1 = ((size_t)(b1 * SEQT + t)) * G + j;
        float xi0 = gx[gxo0],        xf0 = gx[gxo0 + 512];
        float xg0 = gx[gxo0 + 1024], xo0 = gx[gxo0 + 1536];
        float xi1 = gx[gxo1],        xf1 = gx[gxo1 + 512];
        float xg1 = gx[gxo1 + 1024], xo1 = gx[gxo1 + 1536];

        // 6 independent accumulator sets -> throughput-bound HMMA issue
        float ahh[2][4], ahl[2][4], alh[2][4];
#pragma unroll
        for (int m = 0; m < 2; m++)
#pragma unroll
            for (int q = 0; q < 4; q++) { ahh[m][q] = 0.f; ahl[m][q] = 0.f; alh[m][q] = 0.f; }

#pragma unroll 4
        for (int kt = 0; kt < 32; kt++) {
            const uint32_t kb = kt * 32;
            uint32_t a0[4], a1[4], l0[4], l1[4], bhf[2], blf[2];
            ldsm_x4(a0[0], a0[1], a0[2], a0[3], ah_b + kb);
            ldsm_x4(a1[0], a1[1], a1[2], a1[3], ah_b + 16 * HROW + kb);
            ldsm_x4(l0[0], l0[1], l0[2], l0[3], al_b + kb);
            ldsm_x4(l1[0], l1[1], l1[2], l1[3], al_b + 16 * HROW + kb);
            ldsm_x2(bhf[0], bhf[1], bh_b + kb);
            ldsm_x2(blf[0], blf[1], bl_b + kb);
            mma16816(ahh[0], a0, bhf);
            mma16816(ahl[0], a0, blf);
            mma16816(alh[0], l0, bhf);
            mma16816(ahh[1], a1, bhf);
            mma16816(ahl[1], a1, blf);
            mma16816(alh[1], l1, bhf);
        }

        // combine partials and write P tile
        {
            int prow = lane >> 2;
            int pcol = wid * 8 + 2 * (lane & 3);
#pragma unroll
            for (int m = 0; m < 2; m++) {
                int bb = prow + m * 16;
                float q0 = ahh[m][0] + ahl[m][0] + alh[m][0];
                float q1 = ahh[m][1] + ahl[m][1] + alh[m][1];
                float q2 = ahh[m][2] + ahl[m][2] + alh[m][2];
                float q3 = ahh[m][3] + ahl[m][3] + alh[m][3];
                *(float2*)&Pt[bb * PST + pcol]       = make_float2(q0, q1);
                *(float2*)&Pt[(bb + 8) * PST + pcol] = make_float2(q2, q3);
            }
        }
        __syncthreads();

        float gi0 = xi0 + Pt[b0 * PST + Rg0 + 0];
        float gf0 = xf0 + Pt[b0 * PST + Rg0 + 2];
        float gg0 = xg0 + Pt[b0 * PST + Rg0 + 4];
        float go0 = xo0 + Pt[b0 * PST + Rg0 + 6];
        float gi1 = xi1 + Pt[b1 * PST + Rg0 + 0];
        float gf1 = xf1 + Pt[b1 * PST + Rg0 + 2];
        float gg1 = xg1 + Pt[b1 * PST + Rg0 + 4];
        float go1 = xo1 + Pt[b1 * PST + Rg0 + 6];

        c0  = sigm(gf0) * c0 + sigm(gi0) * tanhf(gg0);
        h0v = sigm(go0) * tanhf(c0);
        c1  = sigm(gf1) * c1 + sigm(gi1) * tanhf(gg1);
        h1v = sigm(go1) * tanhf(c1);

        __nv_bfloat16 hh0 = __float2bfloat16(h0v);
        __nv_bfloat16 hl0 = __float2bfloat16(h0v - __bfloat162float(hh0));
        __nv_bfloat16 hh1 = __float2bfloat16(h1v);
        __nv_bfloat16 hl1 = __float2bfloat16(h1v - __bfloat162float(hh1));
        g_hb16[dir][s & 1][0][b0 * HID + j] = hh0;
        g_hb16[dir][s & 1][1][b0 * HID + j] = hl0;
        g_hb16[dir][s & 1][0][b1 * HID + j] = hh1;
        g_hb16[dir][s & 1][1][b1 * HID + j] = hl1;
        if (layer == 0) {
            size_t r0o = ((size_t)(b0 * SEQT + t)) * INP + dir * HID + j;
            size_t r1o = ((size_t)(b1 * SEQT + t)) * INP + dir * HID + j;
            g_l1hi[r0o] = hh0; g_l1lo[r0o] = hl0;
            g_l1hi[r1o] = hh1; g_l1lo[r1o] = hl1;
        } else {
            dout[((size_t)b0 * SEQT + t) * (2 * HID) + dir * HID + j] = h0v;
            dout[((size_t)b1 * SEQT + t) * (2 * HID) + dir * HID + j] = h1v;
        }

        if (s < SEQT - 1) {
            __syncthreads();
            if (tid == 0) {
                __threadfence();
                unsigned arr = atomicAdd(&g_bar[dir], 1u);
                if (arr == 63u) {
                    atomicExch(&g_bar[dir], 0u);
                    __threadfence();
                    atomicAdd(&g_gen[dir], 1u);
                } else {
                    unsigned target = (unsigned)(layer * (SEQT - 1) + s + 1);
                    while (*((volatile unsigned*)&g_gen[dir]) < target) { }
                    __threadfence();
                }
            }
            __syncthreads();
        }
    }

    float* hn = dout + (size_t)MROWS * 2 * HID;
    float* cn = hn + (size_t)NC * BATCH * HID;
    size_t o0 = ((size_t)cell * BATCH + b0) * HID + j;
    size_t o1 = ((size_t)cell * BATCH + b1) * HID + j;
    hn[o0] = h0v; hn[o1] = h1v;
    cn[o0] = c0;  cn[o1] = c1;
}

// -------------------- launch --------------------
extern "C" void kernel_launch(void* const* d_in, const int* in_sizes, int n_in,
                              void* d_out, int out_size)
{
    (void)in_sizes; (void)n_in; (void)out_size;
    const float* x     = (const float*)d_in[0];
    const float* w_ih  = (const float*)d_in[1];
    const float* w_hh  = (const float*)d_in[2];
    const float* b_ih  = (const float*)d_in[3];
    const float* b_hh  = (const float*)d_in[4];
    const float* a_ih  = (const float*)d_in[5];
    const float* bl_ih = (const float*)d_in[6];
    const float* a_hh  = (const float*)d_in[7];
    const float* bl_hh = (const float*)d_in[8];
    float* out = (float*)d_out;

    cudaFuncSetAttribute(lstm_rec, cudaFuncAttributeMaxDynamicSharedMemorySize, SMEM_REC);
    cudaFuncSetAttribute(gemm_gx_mma, cudaFuncAttributeMaxDynamicSharedMemorySize, SMEM_GEMM);

    const size_t ntot = NIH + NHH + NXQ;                                       // 16777216
    prep_all<<<(unsigned)(ntot / 256), 256>>>(w_ih, a_ih, bl_ih,
                                              w_hh, a_hh, bl_hh, x);           // 0
    gemm_gx_mma<<<dim3(16, 128, 2), 256, SMEM_GEMM>>>(0, b_ih, b_hh);          // 1
    reset_bar<<<1, 32>>>();                                                    // 2
    lstm_rec<<<128, 128, SMEM_REC>>>(0, out);                                  // 3  <- profiled slot
    gemm_gx_mma<<<dim3(16, 128, 2), 256, SMEM_GEMM>>>(1, b_ih, b_hh);          // 4
    lstm_rec<<<128, 128, SMEM_REC>>>(1, out);                                  // 5
}

// round 16
// speedup vs baseline: 1.3289x; 1.0396x over previous
#include <cuda_runtime.h>
#include <cuda_bf16.h>
#include <cstdint>
#include <string.h>

#define BATCH 32
#define SEQT  512
#define INP   1024
#define HID   512
#define G     2048
#define NC    4
#define RNK   8
#define SCALING 2.0f
#define MROWS 16384   // BATCH*SEQT

// -------------------- device scratch (no allocations allowed) --------------------
__device__ __nv_bfloat16 g_wih_hi[(size_t)NC * G * INP];
__device__ __nv_bfloat16 g_wih_lo[(size_t)NC * G * INP];
__device__ __nv_bfloat16 g_whh_hi[(size_t)NC * G * HID];
__device__ __nv_bfloat16 g_whh_lo[(size_t)NC * G * HID];
__device__ __nv_bfloat16 g_xhi[(size_t)MROWS * INP];
__device__ __nv_bfloat16 g_xlo[(size_t)MROWS * INP];
__device__ __nv_bfloat16 g_l1hi[(size_t)MROWS * INP];
__device__ __nv_bfloat16 g_l1lo[(size_t)MROWS * INP];
__device__ float g_gx[2ull * MROWS * G];
__device__ __nv_bfloat16 g_hb16[2][2][2][BATCH * HID];  // [dir][pingpong][plane hi/lo]
__device__ unsigned g_flag[2][64];
__device__ unsigned g_gen[2];

// -------------------- helpers --------------------
__device__ __forceinline__ uint32_t smem_u32(const void* p)
{
    uint32_t a;
    asm("{ .reg .u64 t; cvta.to.shared.u64 t, %1; cvt.u32.u64 %0, t; }" : "=r"(a) : "l"(p));
    return a;
}
__device__ __forceinline__ void ldsm_x4(uint32_t& r0, uint32_t& r1, uint32_t& r2,
                                        uint32_t& r3, uint32_t addr)
{
    asm volatile("ldmatrix.sync.aligned.m8n8.x4.shared.b16 {%0,%1,%2,%3}, [%4];"
                 : "=r"(r0), "=r"(r1), "=r"(r2), "=r"(r3) : "r"(addr));
}
__device__ __forceinline__ void ldsm_x2(uint32_t& r0, uint32_t& r1, uint32_t addr)
{
    asm volatile("ldmatrix.sync.aligned.m8n8.x2.shared.b16 {%0,%1}, [%2];"
                 : "=r"(r0), "=r"(r1) : "r"(addr));
}
__device__ __forceinline__ void mma16816(float* d, const uint32_t* a, const uint32_t* b)
{
    asm volatile(
        "mma.sync.aligned.m16n8k16.row.col.f32.bf16.bf16.f32 "
        "{%0,%1,%2,%3}, {%4,%5,%6,%7}, {%8,%9}, {%0,%1,%2,%3};"
        : "+f"(d[0]), "+f"(d[1]), "+f"(d[2]), "+f"(d[3])
        : "r"(a[0]), "r"(a[1]), "r"(a[2]), "r"(a[3]), "r"(b[0]), "r"(b[1]));
}
__device__ __forceinline__ void cpasync16(uint32_t saddr, const void* g)
{
    asm volatile("cp.async.cg.shared.global [%0], [%1], 16;"
                 :: "r"(saddr), "l"(__cvta_generic_to_global(g)) : "memory");
}
#define CP_COMMIT() asm volatile("cp.async.commit_group;" ::: "memory")
#define CP_WAIT(n)  asm volatile("cp.async.wait_group %0;" :: "n"(n) : "memory")

__device__ __forceinline__ float sigm(float x) { return 1.f / (1.f + __expf(-x)); }

// -------------------- merged prep --------------------
#define NIH ((size_t)NC * G * INP)
#define NHH ((size_t)NC * G * HID)
#define NXQ ((size_t)MROWS * INP / 4)

__global__ void prep_all(const float* __restrict__ w_ih, const float* __restrict__ a_ih,
                         const float* __restrict__ bl_ih,
                         const float* __restrict__ w_hh, const float* __restrict__ a_hh,
                         const float* __restrict__ bl_hh,
                         const float* __restrict__ x)
{
    size_t idx = (size_t)blockIdx.x * 256 + threadIdx.x;
    if (idx < NIH) {
        int d = (int)(idx % INP);
        int g = (int)((idx / INP) % G);
        int c = (int)(idx / ((size_t)INP * G));
        const float* ar  = a_ih + (size_t)c * RNK * INP + d;
        const float* blr = bl_ih + ((size_t)c * G + g) * RNK;
        float acc = 0.f;
#pragma unroll
        for (int r = 0; r < RNK; r++) acc += blr[r] * ar[(size_t)r * INP];
        float wv = w_ih[idx] + SCALING * acc;
        __nv_bfloat16 hi = __float2bfloat16(wv);
        g_wih_hi[idx] = hi;
        g_wih_lo[idx] = __float2bfloat16(wv - __bfloat162float(hi));
    } else if (idx < NIH + NHH) {
        size_t k = idx - NIH;
        int d = (int)(k % HID);
        int g = (int)((k / HID) % G);
        int c = (int)(k / ((size_t)HID * G));
        const float* ar  = a_hh + (size_t)c * RNK * HID + d;
        const float* blr = bl_hh + ((size_t)c * G + g) * RNK;
        float acc = 0.f;
#pragma unroll
        for (int r = 0; r < RNK; r++) acc += blr[r] * ar[(size_t)r * HID];
        float wv = w_hh[k] + SCALING * acc;
        __nv_bfloat16 hi = __float2bfloat16(wv);
        g_whh_hi[k] = hi;
        g_whh_lo[k] = __float2bfloat16(wv - __bfloat162float(hi));
    } else {
        size_t q = (idx - NIH - NHH) * 4;
        float4 v = *(const float4*)(x + q);
        __nv_bfloat16 h0 = __float2bfloat16(v.x), h1 = __float2bfloat16(v.y);
        __nv_bfloat16 h2 = __float2bfloat16(v.z), h3 = __float2bfloat16(v.w);
        __nv_bfloat16 l0 = __float2bfloat16(v.x - __bfloat162float(h0));
        __nv_bfloat16 l1 = __float2bfloat16(v.y - __bfloat162float(h1));
        __nv_bfloat16 l2 = __float2bfloat16(v.z - __bfloat162float(h2));
        __nv_bfloat16 l3 = __float2bfloat16(v.w - __bfloat162float(h3));
        __nv_bfloat162* hp = (__nv_bfloat162*)(g_xhi + q);
        __nv_bfloat162* lp = (__nv_bfloat162*)(g_xlo + q);
        hp[0] = __nv_bfloat162(h0, h1); hp[1] = __nv_bfloat162(h2, h3);
        lp[0] = __nv_bfloat162(l0, l1); lp[1] = __nv_bfloat162(l2, l3);
    }
}

__global__ void reset_bar()
{
    int t = threadIdx.x;
    if (t < 128) g_flag[t >> 6][t & 63] = 0u;
    if (t < 2) g_gen[t] = 0u;
}

// -------------------- tensor-core gx GEMM (unchanged, passing since R10) --------------------
#define RS     40
#define ABYTES (128 * RS * 2)
#define SMEM_GEMM (4 * ABYTES)

__global__ __launch_bounds__(256) void gemm_gx_mma(int layer,
                                                   const float* __restrict__ b_ih,
                                                   const float* __restrict__ b_hh)
{
    extern __shared__ __align__(16) char smem[];
    const uint32_t sb = smem_u32(smem);
    const int tid = threadIdx.x, wid = tid >> 5, lane = tid & 31;
    const int wm = wid >> 2, wn = wid & 3;
    const int n0 = blockIdx.x * 128, m0 = blockIdx.y * 128, cl = blockIdx.z;
    const int cell = layer * 2 + cl;

    const __nv_bfloat16* Ah = layer ? g_l1hi : g_xhi;
    const __nv_bfloat16* Al = layer ? g_l1lo : g_xlo;
    const __nv_bfloat16* Bh = g_wih_hi + (size_t)cell * G * INP;
    const __nv_bfloat16* Bl = g_wih_lo + (size_t)cell * G * INP;

    float acc[4][4][4];
#pragma unroll
    for (int i = 0; i < 4; i++)
#pragma unroll
        for (int j = 0; j < 4; j++)
#pragma unroll
            for (int q = 0; q < 4; q++) acc[i][j][q] = 0.f;

    const int lrow = tid >> 2, lc8 = (tid & 3) * 8;

    auto load_chunk = [&](int ch, int buf) {
        const int plane = ch >> 5;
        const int kc = (ch & 31) * 32;
        const __nv_bfloat16* Ap = (plane == 2) ? Al : Ah;
        const __nv_bfloat16* Bp = (plane == 1) ? Bl : Bh;
        uint32_t sa = sb + buf * ABYTES;
        uint32_t sB = sb + 2 * ABYTES + buf * ABYTES;
        cpasync16(sa + (lrow * RS + lc8) * 2,        Ap + (size_t)(m0 + lrow)      * INP + kc + lc8);
        cpasync16(sa + ((lrow + 64) * RS + lc8) * 2, Ap + (size_t)(m0 + lrow + 64) * INP + kc + lc8);
        cpasync16(sB + (lrow * RS + lc8) * 2,        Bp + (size_t)(n0 + lrow)      * INP + kc + lc8);
        cpasync16(sB + ((lrow + 64) * RS + lc8) * 2, Bp + (size_t)(n0 + lrow + 64) * INP + kc + lc8);
        CP_COMMIT();
    };

    const int arow = wm * 64 + (lane & 15);
    const int acol_sel = (lane >> 4) * 8;
    const int brow = wn * 32 + (lane & 7);
    const int bcol_sel = ((lane >> 3) & 1) * 8;

    load_chunk(0, 0);

    for (int ch = 0; ch < 96; ch++) {
        const int b = ch & 1;
        if (ch < 95) load_chunk(ch + 1, 1 - b);
        if (ch < 95) { CP_WAIT(1); } else { CP_WAIT(0); }
        __syncthreads();

        const uint32_t sa = sb + b * ABYTES;
        const uint32_t sB = sb + 2 * ABYTES + b * ABYTES;
#pragma unroll
        for (int ks = 0; ks < 2; ks++) {
            uint32_t afr[4][4], bfr[4][2];
#pragma unroll
            for (int mt = 0; mt < 4; mt++) {
                uint32_t addr = sa + ((arow + mt * 16) * RS + ks * 16 + acol_sel) * 2;
                ldsm_x4(afr[mt][0], afr[mt][1], afr[mt][2], afr[mt][3], addr);
            }
#pragma unroll
            for (int nt = 0; nt < 4; nt++) {
                uint32_t addr = sB + ((brow + nt * 8) * RS + ks * 16 + bcol_sel) * 2;
                ldsm_x2(bfr[nt][0], bfr[nt][1], addr);
            }
#pragma unroll
            for (int mt = 0; mt < 4; mt++)
#pragma unroll
                for (int nt = 0; nt < 4; nt++)
                    mma16816(acc[mt][nt], afr[mt], bfr[nt]);
        }
        __syncthreads();
    }

    float bsum[4][2];
#pragma unroll
    for (int nt = 0; nt < 4; nt++) {
        int col = n0 + wn * 32 + nt * 8 + (lane & 3) * 2;
        bsum[nt][0] = b_ih[(size_t)cell * G + col]     + b_hh[(size_t)cell * G + col];
        bsum[nt][1] = b_ih[(size_t)cell * G + col + 1] + b_hh[(size_t)cell * G + col + 1];
    }
    float* gxbase = g_gx + (size_t)cl * MROWS * G;
#pragma unroll
    for (int mt = 0; mt < 4; mt++) {
        int r0 = m0 + wm * 64 + mt * 16 + (lane >> 2);
        float* row0 = gxbase + (size_t)r0 * G;
        float* row1 = row0 + 8 * (size_t)G;
#pragma unroll
        for (int nt = 0; nt < 4; nt++) {
            int col = n0 + wn * 32 + nt * 8 + (lane & 3) * 2;
            float2 v0 = make_float2(acc[mt][nt][0] + bsum[nt][0],
                                    acc[mt][nt][1] + bsum[nt][1]);
            float2 v1 = make_float2(acc[mt][nt][2] + bsum[nt][0],
                                    acc[mt][nt][3] + bsum[nt][1]);
            *(float2*)(row0 + col) = v0;
            *(float2*)(row1 + col) = v1;
        }
    }
}

// -------------------- persistent recurrence v3: 256 thr, k-split warps, flag barrier ---
// 128 CTAs: dir = cta>>6, cg = cta&63 -> units [8cg, 8cg+8).
// 8 warps: nw = wid&3 (n-tile: W rows [8nw,8nw+8)), kh = wid>>2 (k-half 256).
// W rows reordered: smem row R -> gate=(R&7)>>1, unit = j0 + 2*(R>>3) + (R&1).
#define HROW 1040                 // bytes per smem row (520 bf16)
#define SH0  0
#define SH1  (SH0 + 32 * HROW)
#define SW0  (SH1 + 32 * HROW)
#define SW1  (SW0 + 32 * HROW)
#define SP   (SW1 + 32 * HROW)    // 133120
#define PST  34                   // P stride (floats)
#define PBUF (32 * PST)           // floats per k-half partial
#define SMEM_REC (SP + 2 * PBUF * 4 + 128)

__global__ __launch_bounds__(256, 1) void lstm_rec(int layer, float* __restrict__ dout)
{
    extern __shared__ __align__(16) char smc[];
    const uint32_t sb = smem_u32(smc);
    float* Pt = (float*)(smc + SP);

    const int cta  = blockIdx.x;
    const int dir  = cta >> 6;
    const int cg   = cta & 63;
    const int j0   = cg * 8;
    const int cell = layer * 2 + dir;
    const int tid  = threadIdx.x;
    const int wid  = tid >> 5, lane = tid & 31;
    const int nw   = wid & 3, kh = wid >> 2;

    // load W slice (both planes), reordered rows
    {
        const __nv_bfloat16* srcs[2] = { g_whh_hi + (size_t)cell * G * HID,
                                         g_whh_lo + (size_t)cell * G * HID };
        const uint32_t dsts[2] = { SW0, SW1 };
#pragma unroll
        for (int p = 0; p < 2; p++) {
            for (int i = tid; i < 2048; i += 256) {
                int R = i >> 6, k8 = (i & 63) * 8;
                int gate = (R & 7) >> 1;
                int urow = 2 * (R >> 3) + (R & 1);
                const uint4 v = *(const uint4*)(srcs[p] + (size_t)(gate * HID + j0 + urow) * HID + k8);
                *(uint4*)(smc + dsts[p] + R * HROW + k8 * 2) = v;
            }
        }
    }
    for (int i = tid; i < (2 * 32 * HROW) / 4; i += 256) ((uint32_t*)(smc + SH0))[i] = 0u;
    __syncthreads();

    const uint32_t khb = (uint32_t)kh * 512;   // k-half byte offset (256 k * 2B)
    const uint32_t aoff = (uint32_t)((lane & 15) * HROW + (lane >> 4) * 16) + khb;
    const uint32_t boff = (uint32_t)(nw * 8 * HROW + (lane & 7) * HROW + ((lane >> 3) & 1) * 16) + khb;
    const uint32_t ah_b = sb + SH0 + aoff, al_b = sb + SH1 + aoff;
    const uint32_t bh_b = sb + SW0 + boff, bl_b = sb + SW1 + boff;

    const int b  = tid >> 3;            // batch 0..31
    const int u  = tid & 7;             // unit 0..7
    const int j  = j0 + u;
    const int Rg0 = (u >> 1) * 8 + (u & 1);
    const float* gx = g_gx + (size_t)dir * MROWS * G;

    float cst = 0.f, hv = 0.f;

    for (int s = 0; s < SEQT; s++) {
        const int t = dir ? (SEQT - 1 - s) : s;

        // gx loads first (independent of h; land under staging)
        size_t gxo = ((size_t)(b * SEQT + t)) * G + j;
        float xi = gx[gxo],        xf = gx[gxo + 512];
        float xg = gx[gxo + 1024], xo = gx[gxo + 1536];

        if (s > 0) {
            const __nv_bfloat16* s0 = g_hb16[dir][(s - 1) & 1][0];
            const __nv_bfloat16* s1 = g_hb16[dir][(s - 1) & 1][1];
            for (int i = tid; i < 2048; i += 256) {
                int bb = i >> 6, k8 = (i & 63) * 8;
                *(uint4*)(smc + SH0 + bb * HROW + k8 * 2) = *(const uint4*)(s0 + bb * HID + k8);
                *(uint4*)(smc + SH1 + bb * HROW + k8 * 2) = *(const uint4*)(s1 + bb * HID + k8);
            }
            __syncthreads();
        }

        // P-half = Hhi*Whi + Hhi*Wlo + Hlo*Whi over this warp's 256 k
        float acc[2][4];
#pragma unroll
        for (int m = 0; m < 2; m++)
#pragma unroll
            for (int q = 0; q < 4; q++) acc[m][q] = 0.f;

#pragma unroll 4
        for (int kt = 0; kt < 16; kt++) {
            const uint32_t kb = kt * 32;
            uint32_t a0[4], a1[4], l0[4], l1[4], bhf[2], blf[2];
            ldsm_x4(a0[0], a0[1], a0[2], a0[3], ah_b + kb);
            ldsm_x4(a1[0], a1[1], a1[2], a1[3], ah_b + 16 * HROW + kb);
            ldsm_x4(l0[0], l0[1], l0[2], l0[3], al_b + kb);
            ldsm_x4(l1[0], l1[1], l1[2], l1[3], al_b + 16 * HROW + kb);
            ldsm_x2(bhf[0], bhf[1], bh_b + kb);
            ldsm_x2(blf[0], blf[1], bl_b + kb);
            mma16816(acc[0], a0, bhf);
            mma16816(acc[0], a0, blf);
            mma16816(acc[0], l0, bhf);
            mma16816(acc[1], a1, bhf);
            mma16816(acc[1], a1, blf);
            mma16816(acc[1], l1, bhf);
        }

        // write k-half partial to P buffer
        {
            float* Pk = Pt + kh * PBUF;
            int prow = lane >> 2;
            int pcol = nw * 8 + 2 * (lane & 3);
#pragma unroll
            for (int m = 0; m < 2; m++) {
                int bb = prow + m * 16;
                *(float2*)&Pk[bb * PST + pcol]       = make_float2(acc[m][0], acc[m][1]);
                *(float2*)&Pk[(bb + 8) * PST + pcol] = make_float2(acc[m][2], acc[m][3]);
            }
        }
        __syncthreads();

        // epilogue: thread = (1 batch, 1 unit); sum the two k-half partials
        float gi = xi + Pt[b * PST + Rg0 + 0] + Pt[PBUF + b * PST + Rg0 + 0];
        float gf = xf + Pt[b * PST + Rg0 + 2] + Pt[PBUF + b * PST + Rg0 + 2];
        float gg = xg + Pt[b * PST + Rg0 + 4] + Pt[PBUF + b * PST + Rg0 + 4];
        float go = xo + Pt[b * PST + Rg0 + 6] + Pt[PBUF + b * PST + Rg0 + 6];

        cst = sigm(gf) * cst + sigm(gi) * tanhf(gg);
        hv  = sigm(go) * tanhf(cst);

        __nv_bfloat16 hh = __float2bfloat16(hv);
        __nv_bfloat16 hl = __float2bfloat16(hv - __bfloat162float(hh));
        g_hb16[dir][s & 1][0][b * HID + j] = hh;
        g_hb16[dir][s & 1][1][b * HID + j] = hl;
        if (layer == 0) {
            size_t ro = ((size_t)(b * SEQT + t)) * INP + dir * HID + j;
            g_l1hi[ro] = hh; g_l1lo[ro] = hl;
        } else {
            dout[((size_t)b * SEQT + t) * (2 * HID) + dir * HID + j] = hv;
        }

        if (s < SEQT - 1) {
            __syncthreads();                     // all h writes issued
            unsigned target = (unsigned)(layer * (SEQT - 1) + s + 1);
            if (tid == 0) {
                __threadfence();
                *(volatile unsigned*)&g_flag[dir][cg] = target;   // own flag: no contention
            }
            if (cg == 0) {
                if (tid < 32) {                  // master warp polls all 64 flags
                    bool ok;
                    do {
                        unsigned f0 = *(volatile unsigned*)&g_flag[dir][tid];
                        unsigned f1 = *(volatile unsigned*)&g_flag[dir][tid + 32];
                        ok = (f0 >= target) && (f1 >= target);
                    } while (!__all_sync(0xFFFFFFFFu, ok));
                    if (tid == 0) {
                        __threadfence();
                        *(volatile unsigned*)&g_gen[dir] = target;
                    }
                }
            } else {
                if (tid == 0) {
                    while (*(volatile unsigned*)&g_gen[dir] < target) { }
                    __threadfence();
                }
            }
            __syncthreads();
        }
    }

    float* hn = dout + (size_t)MROWS * 2 * HID;
    float* cn = hn + (size_t)NC * BATCH * HID;
    size_t o = ((size_t)cell * BATCH + b) * HID + j;
    hn[o] = hv;
    cn[o] = cst;
}

// -------------------- launch --------------------
extern "C" void kernel_launch(void* const* d_in, const int* in_sizes, int n_in,
                              void* d_out, int out_size)
{
    (void)in_sizes; (void)n_in; (void)out_size;
    const float* x     = (const float*)d_in[0];
    const float* w_ih  = (const float*)d_in[1];
    const float* w_hh  = (const float*)d_in[2];
    const float* b_ih  = (const float*)d_in[3];
    const float* b_hh  = (const float*)d_in[4];
    const float* a_ih  = (const float*)d_in[5];
    const float* bl_ih = (const float*)d_in[6];
    const float* a_hh  = (const float*)d_in[7];
    const float* bl_hh = (const float*)d_in[8];
    float* out = (float*)d_out;

    cudaFuncSetAttribute(lstm_rec, cudaFuncAttributeMaxDynamicSharedMemorySize, SMEM_REC);
    cudaFuncSetAttribute(gemm_gx_mma, cudaFuncAttributeMaxDynamicSharedMemorySize, SMEM_GEMM);

    const size_t ntot = NIH + NHH + NXQ;
    prep_all<<<(unsigned)(ntot / 256), 256>>>(w_ih, a_ih, bl_ih,
                                              w_hh, a_hh, bl_hh, x);           // 0
    gemm_gx_mma<<<dim3(16, 128, 2), 256, SMEM_GEMM>>>(0, b_ih, b_hh);          // 1
    reset_bar<<<1, 128>>>();                                                   // 2
    lstm_rec<<<128, 256, SMEM_REC>>>(0, out);                                  // 3  <- profiled slot
    gemm_gx_mma<<<dim3(16, 128, 2), 256, SMEM_GEMM>>>(1, b_ih, b_hh);          // 4
    lstm_rec<<<128, 256, SMEM_REC>>>(1, out);                                  // 5
}